// round 1
// baseline (speedup 1.0000x reference)
#include <cuda_runtime.h>
#include <cstddef>

// Problem shape
#define BATCH 4096
#define FN    1024     // FILTER_NUM
#define RC    19       // REL_CNT
#define RD    1024     // REL_DIM
#define FLAT  (FN * RC)            // 19456 floats per batch row of conv
#define NBLK  512                  // grid of main kernel
#define NB_PER (BATCH / NBLK)      // 8 batches per block
#define RED_STRIDE 21              // odd stride -> conflict-free 32-bit banks
#define SMEM_FLOATS (FLAT + 256 * RED_STRIDE)   // 19456 + 5376 = 24832
#define SMEM_BYTES  (SMEM_FLOATS * 4)           // 99328 B

// Scratch for W[f][r] = sum_e U[f,e] * R[r,e]  (flat layout matching conv's [f*19+r])
__device__ float g_W[FLAT];

// ---------------------------------------------------------------------------
// Kernel 1: W = U @ R^T   (1024 x 19 x 1024 = 20 M-MACs, trivial)
// grid 128 blocks x 256 threads; warp w of block b computes f = b*8 + w.
// U row cached in 32 regs/lane; R rows hit L1 after first warp touches them.
// ---------------------------------------------------------------------------
__global__ void compute_w_kernel(const float* __restrict__ U,
                                 const float* __restrict__ R) {
    const int warp = threadIdx.x >> 5;
    const int lane = threadIdx.x & 31;
    const int f = blockIdx.x * 8 + warp;

    const float4* u4 = reinterpret_cast<const float4*>(U + (size_t)f * RD);
    float4 u[8];
#pragma unroll
    for (int i = 0; i < 8; i++) u[i] = u4[lane + 32 * i];

    for (int r = 0; r < RC; r++) {
        const float4* r4 = reinterpret_cast<const float4*>(R + (size_t)r * RD);
        float s = 0.f;
#pragma unroll
        for (int i = 0; i < 8; i++) {
            float4 rv = r4[lane + 32 * i];
            s += u[i].x * rv.x + u[i].y * rv.y + u[i].z * rv.z + u[i].w * rv.w;
        }
#pragma unroll
        for (int off = 16; off > 0; off >>= 1)
            s += __shfl_xor_sync(0xffffffffu, s, off);
        if (lane == 0) g_W[f * RC + r] = s;
    }
}

// ---------------------------------------------------------------------------
// Kernel 2: score[b][r] = sum_f conv[b][f][r] * W[f][r]
// One block per batch-stream, 8 batches each. conv[b] streamed as unit-stride
// float4 (perfect coalescing, 1 line per warp-LDG). Accumulation into 19
// rotating register slots with compile-time indices:
//   idx = it*1024 + 4*tid + j  ->  r = (17*it + 4*tid + j) mod 19
//   slot k = (17*it + j) mod 19  (constant per unrolled (it,j))
// ---------------------------------------------------------------------------
__global__ __launch_bounds__(256, 2)
void score_kernel(const float* __restrict__ conv, float* __restrict__ out) {
    extern __shared__ float sm[];
    float* sW  = sm;            // FLAT floats
    float* red = sm + FLAT;     // 256 * RED_STRIDE floats

    const int tid = threadIdx.x;

    // Load W into shared once per block (amortized over NB_PER batches).
    float4* sW4 = reinterpret_cast<float4*>(sW);
    const float4* gW4 = reinterpret_cast<const float4*>(g_W);
#pragma unroll
    for (int k = 0; k < 19; k++)
        sW4[tid + 256 * k] = gW4[tid + 256 * k];
    __syncthreads();

    const int r0 = (4 * tid) % RC;   // residue base of this thread's slot 0

    for (int ib = 0; ib < NB_PER; ib++) {
        const int b = blockIdx.x + NBLK * ib;
        const float4* c4 = reinterpret_cast<const float4*>(conv + (size_t)b * FLAT);

        float acc[RC];
#pragma unroll
        for (int k = 0; k < RC; k++) acc[k] = 0.f;

#pragma unroll
        for (int it = 0; it < 19; it++) {
            float4 cv = __ldcs(&c4[it * 256 + tid]);   // streaming: read-once data
            float4 wv = sW4[it * 256 + tid];
            acc[(17 * it + 0) % RC] += cv.x * wv.x;
            acc[(17 * it + 1) % RC] += cv.y * wv.y;
            acc[(17 * it + 2) % RC] += cv.z * wv.z;
            acc[(17 * it + 3) % RC] += cv.w * wv.w;
        }

        // Scatter rotated accumulators into this thread's shared row.
        float* myrow = red + tid * RED_STRIDE;
#pragma unroll
        for (int k = 0; k < RC; k++) {
            int r = r0 + k;
            if (r >= RC) r -= RC;
            myrow[r] = acc[k];
        }

        // Block tree reduction over 256 rows (stride-21: conflict-free).
#pragma unroll
        for (int s = 128; s >= 1; s >>= 1) {
            __syncthreads();
            if (tid < s) {
#pragma unroll
                for (int r = 0; r < RC; r++)
                    red[tid * RED_STRIDE + r] += red[(tid + s) * RED_STRIDE + r];
            }
        }
        __syncthreads();

        if (tid < RC)
            out[(size_t)b * RC + tid] = red[tid];   // row 0, col tid

        __syncthreads();   // protect red before next batch's scatter
    }
}

// ---------------------------------------------------------------------------
// Launch
// ---------------------------------------------------------------------------
extern "C" void kernel_launch(void* const* d_in, const int* in_sizes, int n_in,
                              void* d_out, int out_size) {
    // Resolve inputs by element count (robust to ordering):
    //   conv_output: 4096*1024*19 = 79,691,776
    //   R_output:    19*1024     = 19,456
    //   U:           1024*1024   = 1,048,576
    const float* conv = nullptr;
    const float* R    = nullptr;
    const float* U    = nullptr;
    for (int i = 0; i < n_in; i++) {
        long long n = in_sizes[i];
        if (n == (long long)BATCH * FN * RC)      conv = (const float*)d_in[i];
        else if (n == (long long)RC * RD)         R    = (const float*)d_in[i];
        else if (n == (long long)FN * RD)         U    = (const float*)d_in[i];
    }
    float* out = (float*)d_out;

    cudaFuncSetAttribute(score_kernel,
                         cudaFuncAttributeMaxDynamicSharedMemorySize, SMEM_BYTES);

    compute_w_kernel<<<128, 256>>>(U, R);
    score_kernel<<<NBLK, 256, SMEM_BYTES>>>(conv, out);
}

// round 2
// speedup vs baseline: 1.4322x; 1.4322x over previous
#include <cuda_runtime.h>
#include <cstddef>

// Problem shape
#define BATCH 4096
#define FN    1024     // FILTER_NUM
#define RC    19       // REL_CNT
#define RD    1024     // REL_DIM
#define FLAT  (FN * RC)            // 19456 floats per batch row of conv

// W[f][r] = sum_e U[f,e] * R[r,e]  (flat layout matching conv's [f*19+r])
__device__ float g_W[FLAT];

// ---------------------------------------------------------------------------
// Kernel 1: W = U @ R^T. One warp per (f, r) pair: 19456 warps.
// Each lane loads 8 float4 of U-row and R-row, dot, then shfl-reduce.
// U rows hit L2/L1 (each re-read by 19 warps), R rows L2-resident (76 KB).
// ---------------------------------------------------------------------------
__global__ void compute_w_kernel(const float* __restrict__ U,
                                 const float* __restrict__ R) {
    const int gw   = blockIdx.x * 8 + (threadIdx.x >> 5);   // 0..19455
    const int lane = threadIdx.x & 31;
    if (gw >= FN * RC) return;
    const int f = gw / RC;
    const int r = gw % RC;

    const float4* u4 = reinterpret_cast<const float4*>(U + (size_t)f * RD);
    const float4* r4 = reinterpret_cast<const float4*>(R + (size_t)r * RD);

    float s = 0.f;
#pragma unroll
    for (int i = 0; i < 8; i++) {
        float4 u  = u4[lane + 32 * i];
        float4 rv = r4[lane + 32 * i];
        s += u.x * rv.x + u.y * rv.y + u.z * rv.z + u.w * rv.w;
    }
#pragma unroll
    for (int off = 16; off > 0; off >>= 1)
        s += __shfl_xor_sync(0xffffffffu, s, off);
    if (lane == 0) g_W[gw] = s;
}

// ---------------------------------------------------------------------------
// Kernel 2: score[b][r] = sum_f conv[b][f][r] * W[f][r]
//
// One WARP per batch. The warp streams conv[b] as 152 unit-stride float4
// loads (perfect coalescing: each warp-LDG touches exactly 4 consecutive
// 128B lines). W is read from global and stays L1-resident (76 KB << 228 KB
// L1; conv uses __ldcs evict-first so it can't thrash W).
//
// Rotating register accumulators with compile-time slots:
//   flat idx = i*128 + 4*lane + j,  r = idx mod 19
//   per-lane residue base r0 = (4*lane) mod 19
//   slot k = (14*i + j) mod 19   (128 mod 19 = 14; constant under unroll,
//   i = o*19 + t makes it (14*t + j) mod 19, independent of o)
//
// Reduction: warp shuffle butterfly with residue correction. After
// shfl_down(d), the peer slot matching our r is (k - 4d) mod 19 — a
// compile-time rotation. No __syncthreads anywhere; no shared memory at all.
// ---------------------------------------------------------------------------
__global__ __launch_bounds__(256, 4)
void score_kernel(const float* __restrict__ conv, float* __restrict__ out) {
    const int lane = threadIdx.x & 31;
    const int b    = blockIdx.x * 8 + (threadIdx.x >> 5);   // warp-per-batch

    const float4* c4 = reinterpret_cast<const float4*>(conv + (size_t)b * FLAT);
    const float4* w4 = reinterpret_cast<const float4*>(g_W);

    float acc[RC];
#pragma unroll
    for (int k = 0; k < RC; k++) acc[k] = 0.f;

    // 152 warp-iterations = 8 outer x 19 inner (slot pattern period = 19)
    for (int o = 0; o < 8; o++) {
        const int base = o * (19 * 32) + lane;
#pragma unroll
        for (int t = 0; t < 19; t++) {
            float4 cv = __ldcs(&c4[base + t * 32]);   // streaming, read-once
            float4 wv = w4[base + t * 32];            // L1-resident
            acc[(14 * t + 0) % RC] += cv.x * wv.x;
            acc[(14 * t + 1) % RC] += cv.y * wv.y;
            acc[(14 * t + 2) % RC] += cv.z * wv.z;
            acc[(14 * t + 3) % RC] += cv.w * wv.w;
        }
    }

    // Warp butterfly reduction with static residue rotation.
    // acc_lane_l[k] corresponds to r = (4l + k) mod 19; peer at lane l+d
    // holds the same r in slot (k - 4d) mod 19.
#pragma unroll
    for (int d = 16; d >= 1; d >>= 1) {
        float tmp[RC];
#pragma unroll
        for (int k = 0; k < RC; k++) {
            const int s = (k + 4 * RC - 4 * d) % RC;   // (k - 4d) mod 19, non-neg
            tmp[k] = __shfl_down_sync(0xffffffffu, acc[s], d);
        }
#pragma unroll
        for (int k = 0; k < RC; k++) acc[k] += tmp[k];
    }

    // Lane 0: r0 = 0, so slot k == relation r.
    if (lane == 0) {
        float* ob = out + (size_t)b * RC;
#pragma unroll
        for (int k = 0; k < RC; k++) ob[k] = acc[k];
    }
}

// ---------------------------------------------------------------------------
// Launch
// ---------------------------------------------------------------------------
extern "C" void kernel_launch(void* const* d_in, const int* in_sizes, int n_in,
                              void* d_out, int out_size) {
    const float* conv = nullptr;
    const float* R    = nullptr;
    const float* U    = nullptr;
    for (int i = 0; i < n_in; i++) {
        long long n = in_sizes[i];
        if (n == (long long)BATCH * FN * RC)      conv = (const float*)d_in[i];
        else if (n == (long long)RC * RD)         R    = (const float*)d_in[i];
        else if (n == (long long)FN * RD)         U    = (const float*)d_in[i];
    }
    float* out = (float*)d_out;

    // 19456 (f,r) warps / 8 warps-per-block = 2432 blocks
    compute_w_kernel<<<2432, 256>>>(U, R);
    // 4096 batch warps / 8 warps-per-block = 512 blocks (single wave @ 4/SM)
    score_kernel<<<512, 256>>>(conv, out);
}